// round 2
// baseline (speedup 1.0000x reference)
#include <cuda_runtime.h>

// Problem-fixed maxima (setup_inputs: N=100000, E=1600000, F=H=128)
#define MAX_N 100000

// -------- scratch (static device globals; no allocation) --------
__device__ __align__(16) float g_dinv[MAX_N];            // deg -> dinv in place
__device__ __align__(16) float g_acc[MAX_N];             // layer-2 scalar scatter accum
__device__ __align__(16) float g_p[MAX_N];               // h . w2_0
__device__ __align__(16) float g_g[MAX_N];               // h . w2_1
__device__ __align__(16) float g_agg[MAX_N * 128];       // A_norm @ x   (51.2 MB)

// ---------------- zero scratch ----------------
__global__ void k_zero(int n) {
    size_t tid = (size_t)blockIdx.x * blockDim.x + threadIdx.x;
    size_t stride = (size_t)gridDim.x * blockDim.x;
    float4* aggv = reinterpret_cast<float4*>(g_agg);
    size_t tot4 = (size_t)n * 32;
    for (size_t i = tid; i < tot4; i += stride) aggv[i] = make_float4(0.f, 0.f, 0.f, 0.f);
    for (size_t i = tid; i < (size_t)n; i += stride) { g_dinv[i] = 0.f; g_acc[i] = 0.f; }
}

// ---------------- degree (count over src) ----------------
__global__ void k_deg(const int* __restrict__ src, int E) {
    int e = blockIdx.x * blockDim.x + threadIdx.x;
    if (e < E) atomicAdd(&g_dinv[src[e]], 1.0f);
}

__global__ void k_dinv(int n) {
    int i = blockIdx.x * blockDim.x + threadIdx.x;
    if (i < n) {
        float d = g_dinv[i];
        g_dinv[i] = (d > 0.f) ? rsqrtf(d) : 0.f;
    }
}

// ---------------- layer-1 scatter: agg[dst] += norm * x[src] ----------------
// one warp per edge, lane l handles 4 contiguous floats, vectorized red
__global__ void k_scatter_vec(const float4* __restrict__ x4,
                              const int* __restrict__ src,
                              const int* __restrict__ dst, int E) {
    int gtid = blockIdx.x * blockDim.x + threadIdx.x;
    int e = gtid >> 5;
    int lane = gtid & 31;
    if (e >= E) return;
    int s = src[e];
    int d = dst[e];
    float nrm = -g_dinv[s] * g_dinv[d];
    float4 v = x4[(size_t)s * 32 + lane];
    float* p = &g_agg[(size_t)d * 128 + lane * 4];
    asm volatile("red.global.add.v4.f32 [%0], {%1,%2,%3,%4};"
                 :: "l"(p), "f"(v.x * nrm), "f"(v.y * nrm), "f"(v.z * nrm), "f"(v.w * nrm)
                 : "memory");
}

// ---------------- packed-f32x2 helpers ----------------
__device__ __forceinline__ void fma2(unsigned long long& acc, unsigned long long a,
                                     unsigned long long b) {
    asm("fma.rn.f32x2 %0, %1, %2, %0;" : "+l"(acc) : "l"(a), "l"(b));
}
__device__ __forceinline__ unsigned long long pk2(float v) {
    unsigned long long r;
    asm("mov.b64 %0, {%1, %1};" : "=l"(r) : "f"(v));
    return r;
}
__device__ __forceinline__ float2 upk(unsigned long long v) {
    float2 r;
    asm("mov.b64 {%0, %1}, %2;" : "=f"(r.x), "=f"(r.y) : "l"(v));
    return r;
}

#define AS_STRIDE 65
#define SMEM_BS_FLOATS (256 * 128)
#define SMEM_AS_FLOATS (2 * 16 * AS_STRIDE)
#define SMEM_TOTAL_BYTES ((SMEM_BS_FLOATS + SMEM_AS_FLOATS + 3 * 128) * 4)

// ---------------- fused GEMM + epilogue ----------------
// Z = [x | agg] @ [w1_0 ; w1_1]  (M=n, K=256, N=128), then
// h = relu(Z + b1);  p = h.w2_0;  g = h.w2_1   (h never stored)
// Block: 64 nodes x 128 cols, 256 threads (16x16), thread = 4 nodes x 4 col-pairs
__global__ __launch_bounds__(256, 1) void k_gemm(
    const float* __restrict__ x,
    const float* __restrict__ w10, const float* __restrict__ w11,
    const float* __restrict__ b1,
    const float* __restrict__ w20, const float* __restrict__ w21, int n)
{
    extern __shared__ float sm[];
    float* Bs = sm;                              // [256][128]
    float* As = sm + SMEM_BS_FLOATS;             // [2][16][AS_STRIDE]
    float* sb1 = As + SMEM_AS_FLOATS;            // [128]
    float* sw20 = sb1 + 128;                     // [128]
    float* sw21 = sw20 + 128;                    // [128]

    int tid = threadIdx.x;
    int tx = tid & 15, ty = tid >> 4;
    int m0 = blockIdx.x * 64;

    // Load W into smem: rows 0..127 = w1_0, 128..255 = w1_1 (each 128x128 row-major)
    {
        float4* bsv = (float4*)Bs;
        const float4* a = (const float4*)w10;
        const float4* b = (const float4*)w11;
        #pragma unroll
        for (int i = 0; i < 16; ++i) bsv[tid + 256 * i] = a[tid + 256 * i];
        #pragma unroll
        for (int i = 0; i < 16; ++i) bsv[4096 + tid + 256 * i] = b[tid + 256 * i];
    }
    if (tid < 128) { sb1[tid] = b1[tid]; sw20[tid] = w20[tid]; sw21[tid] = w21[tid]; }

    // A-tile loader mapping: 256 threads -> 64 rows x 4 quads of 4 k-values
    int arow = tid >> 2, aq = tid & 3;
    int gm = m0 + arow;
    int gmc = (gm < n) ? gm : (n - 1);
    const float* xrow = x + (size_t)gmc * 128;
    const float* grow = g_agg + (size_t)gmc * 128;

    // preload tile 0 (k 0..15 of x)
    float4 av = *(const float4*)(xrow + aq * 4);
    {
        float* Aw = As;  // buf 0
        Aw[(aq * 4 + 0) * AS_STRIDE + arow] = av.x;
        Aw[(aq * 4 + 1) * AS_STRIDE + arow] = av.y;
        Aw[(aq * 4 + 2) * AS_STRIDE + arow] = av.z;
        Aw[(aq * 4 + 3) * AS_STRIDE + arow] = av.w;
    }
    __syncthreads();

    unsigned long long acc[4][4];
    #pragma unroll
    for (int i = 0; i < 4; ++i)
        #pragma unroll
        for (int j = 0; j < 4; ++j) acc[i][j] = 0ULL;

    int buf = 0;
    #pragma unroll 1
    for (int t = 0; t < 16; ++t) {
        float4 nxt;
        if (t < 15) {
            int tk = t + 1;
            const float* srcrow = (tk < 8) ? xrow : grow;
            nxt = *(const float4*)(srcrow + ((tk & 7) * 16 + aq * 4));
        }
        const float* Ab = As + buf * 16 * AS_STRIDE;
        const float* Bb = Bs + (t * 16) * 128;
        #pragma unroll
        for (int kk = 0; kk < 16; ++kk) {
            float a0 = Ab[kk * AS_STRIDE + ty];
            float a1 = Ab[kk * AS_STRIDE + ty + 16];
            float a2 = Ab[kk * AS_STRIDE + ty + 32];
            float a3 = Ab[kk * AS_STRIDE + ty + 48];
            unsigned long long ap0 = pk2(a0), ap1 = pk2(a1);
            unsigned long long ap2 = pk2(a2), ap3 = pk2(a3);
            const unsigned long long* brow = (const unsigned long long*)(Bb + kk * 128);
            unsigned long long b0 = brow[tx];        // cols 2tx, 2tx+1
            unsigned long long b1v = brow[tx + 16];  // cols 2tx+32, ..
            unsigned long long b2v = brow[tx + 32];  // cols 2tx+64
            unsigned long long b3v = brow[tx + 48];  // cols 2tx+96
            fma2(acc[0][0], ap0, b0); fma2(acc[0][1], ap0, b1v);
            fma2(acc[0][2], ap0, b2v); fma2(acc[0][3], ap0, b3v);
            fma2(acc[1][0], ap1, b0); fma2(acc[1][1], ap1, b1v);
            fma2(acc[1][2], ap1, b2v); fma2(acc[1][3], ap1, b3v);
            fma2(acc[2][0], ap2, b0); fma2(acc[2][1], ap2, b1v);
            fma2(acc[2][2], ap2, b2v); fma2(acc[2][3], ap2, b3v);
            fma2(acc[3][0], ap3, b0); fma2(acc[3][1], ap3, b1v);
            fma2(acc[3][2], ap3, b2v); fma2(acc[3][3], ap3, b3v);
        }
        if (t < 15) {
            // safe: buf^1 was last read in iter t-1 (barrier at end of t-1)
            float* Aw = As + (buf ^ 1) * 16 * AS_STRIDE;
            Aw[(aq * 4 + 0) * AS_STRIDE + arow] = nxt.x;
            Aw[(aq * 4 + 1) * AS_STRIDE + arow] = nxt.y;
            Aw[(aq * 4 + 2) * AS_STRIDE + arow] = nxt.z;
            Aw[(aq * 4 + 3) * AS_STRIDE + arow] = nxt.w;
            buf ^= 1;
        }
        __syncthreads();
    }

    // Epilogue: bias + relu + dots with w2_0/w2_1, reduce over the 16 tx lanes
    #pragma unroll
    for (int i = 0; i < 4; ++i) {
        int m = m0 + ty + 16 * i;
        float p = 0.f, g = 0.f;
        #pragma unroll
        for (int j = 0; j < 4; ++j) {
            float2 v = upk(acc[i][j]);
            int c = 2 * tx + 32 * j;
            float h0 = fmaxf(v.x + sb1[c], 0.f);
            float h1 = fmaxf(v.y + sb1[c + 1], 0.f);
            p = fmaf(h0, sw20[c], fmaf(h1, sw20[c + 1], p));
            g = fmaf(h0, sw21[c], fmaf(h1, sw21[c + 1], g));
        }
        #pragma unroll
        for (int off = 8; off >= 1; off >>= 1) {
            p += __shfl_xor_sync(0xffffffffu, p, off);
            g += __shfl_xor_sync(0xffffffffu, g, off);
        }
        if (tx == 0 && m < n) { g_p[m] = p; g_g[m] = g; }
    }
}

// ---------------- layer-2 scalar scatter: acc[dst] += norm * g[src] ----------------
__global__ void k_scatter_scalar(const int* __restrict__ src,
                                 const int* __restrict__ dst, int E) {
    int e = blockIdx.x * blockDim.x + threadIdx.x;
    if (e < E) {
        int s = src[e];
        int d = dst[e];
        float v = -g_dinv[s] * g_dinv[d] * g_g[s];
        atomicAdd(&g_acc[d], v);
    }
}

// ---------------- output: sigmoid(p + acc + b2) ----------------
__global__ void k_out(const float* __restrict__ b2, float* __restrict__ out, int n) {
    int i = blockIdx.x * blockDim.x + threadIdx.x;
    if (i < n) {
        float z = g_p[i] + g_acc[i] + b2[0];
        out[i] = 1.0f / (1.0f + expf(-z));
    }
}

extern "C" void kernel_launch(void* const* d_in, const int* in_sizes, int n_in,
                              void* d_out, int out_size) {
    const float* x   = (const float*)d_in[0];
    const int*   ei  = (const int*)d_in[1];
    const float* w10 = (const float*)d_in[2];
    const float* w11 = (const float*)d_in[3];
    const float* b1  = (const float*)d_in[4];
    const float* w20 = (const float*)d_in[5];
    const float* w21 = (const float*)d_in[6];
    const float* b2  = (const float*)d_in[7];
    float* out = (float*)d_out;

    int n = in_sizes[0] / 128;
    int E = in_sizes[1] / 2;
    const int* src = ei;
    const int* dst = ei + E;

    k_zero<<<2048, 256>>>(n);
    k_deg<<<(E + 255) / 256, 256>>>(src, E);
    k_dinv<<<(n + 255) / 256, 256>>>(n);
    k_scatter_vec<<<(E + 7) / 8, 256>>>((const float4*)x, src, dst, E);

    cudaFuncSetAttribute(k_gemm, cudaFuncAttributeMaxDynamicSharedMemorySize,
                         SMEM_TOTAL_BYTES);
    k_gemm<<<(n + 63) / 64, 256, SMEM_TOTAL_BYTES>>>(x, w10, w11, b1, w20, w21, n);

    k_scatter_scalar<<<(E + 255) / 256, 256>>>(src, dst, E);
    k_out<<<(n + 255) / 256, 256>>>(b2, out, n);
}

// round 3
// speedup vs baseline: 1.0891x; 1.0891x over previous
#include <cuda_runtime.h>

// Problem-fixed maxima (setup_inputs: N=100000, E=1600000, F=H=128)
#define MAX_N 100000

// -------- scratch (static device globals; no allocation) --------
__device__ __align__(16) float g_dinv[MAX_N];            // deg -> dinv in place
__device__ __align__(16) float g_acc[MAX_N];             // layer-2 scalar scatter accum
__device__ __align__(16) float g_p[MAX_N];               // h . w2_0
__device__ __align__(16) float g_g[MAX_N];               // h . w2_1
__device__ __align__(16) float g_agg[MAX_N * 128];       // A_norm @ x   (51.2 MB)

// ---------------- zero scratch ----------------
__global__ void k_zero(int n) {
    size_t tid = (size_t)blockIdx.x * blockDim.x + threadIdx.x;
    size_t stride = (size_t)gridDim.x * blockDim.x;
    float4* aggv = reinterpret_cast<float4*>(g_agg);
    size_t tot4 = (size_t)n * 32;
    for (size_t i = tid; i < tot4; i += stride) aggv[i] = make_float4(0.f, 0.f, 0.f, 0.f);
    for (size_t i = tid; i < (size_t)n; i += stride) { g_dinv[i] = 0.f; g_acc[i] = 0.f; }
}

// ---------------- degree (count over src) ----------------
__global__ void k_deg(const int* __restrict__ src, int E) {
    int e = blockIdx.x * blockDim.x + threadIdx.x;
    if (e < E) atomicAdd(&g_dinv[src[e]], 1.0f);
}

__global__ void k_dinv(int n) {
    int i = blockIdx.x * blockDim.x + threadIdx.x;
    if (i < n) {
        float d = g_dinv[i];
        g_dinv[i] = (d > 0.f) ? rsqrtf(d) : 0.f;
    }
}

// ---------------- layer-1 scatter: agg[dst] += norm * x[src] ----------------
// one warp handles SC_U edges, batch-loaded for MLP; lane l covers 4 floats
#define SC_U 8
__global__ __launch_bounds__(256) void k_scatter_vec(
    const float4* __restrict__ x4,
    const int* __restrict__ src,
    const int* __restrict__ dst, int E)
{
    int warp = (blockIdx.x * blockDim.x + threadIdx.x) >> 5;
    int lane = threadIdx.x & 31;
    int base = warp * SC_U;
    if (base >= E) return;

    int s[SC_U], d[SC_U];
    #pragma unroll
    for (int u = 0; u < SC_U; ++u) {
        int e = base + u;
        e = (e < E) ? e : (E - 1);
        s[u] = __ldg(&src[e]);
        d[u] = __ldg(&dst[e]);
    }
    float nrm[SC_U];
    #pragma unroll
    for (int u = 0; u < SC_U; ++u)
        nrm[u] = -g_dinv[s[u]] * g_dinv[d[u]];

    float4 v[SC_U];
    #pragma unroll
    for (int u = 0; u < SC_U; ++u)
        v[u] = x4[(size_t)s[u] * 32 + lane];

    #pragma unroll
    for (int u = 0; u < SC_U; ++u) {
        if (base + u < E) {
            float* p = &g_agg[(size_t)d[u] * 128 + lane * 4];
            asm volatile("red.global.add.v4.f32 [%0], {%1,%2,%3,%4};"
                         :: "l"(p), "f"(v[u].x * nrm[u]), "f"(v[u].y * nrm[u]),
                            "f"(v[u].z * nrm[u]), "f"(v[u].w * nrm[u])
                         : "memory");
        }
    }
}

// ---------------- packed-f32x2 helpers ----------------
__device__ __forceinline__ void fma2(unsigned long long& acc, unsigned long long a,
                                     unsigned long long b) {
    asm("fma.rn.f32x2 %0, %1, %2, %0;" : "+l"(acc) : "l"(a), "l"(b));
}
__device__ __forceinline__ unsigned long long pk2(float v) {
    unsigned long long r;
    asm("mov.b64 %0, {%1, %1};" : "=l"(r) : "f"(v));
    return r;
}
__device__ __forceinline__ float2 upk(unsigned long long v) {
    float2 r;
    asm("mov.b64 {%0, %1}, %2;" : "=f"(r.x), "=f"(r.y) : "l"(v));
    return r;
}

// A tile stored PRE-DUPLICATED as f32x2 (ull) pairs: As2[buf][k][row], stride 65 ull
#define AS_STRIDE 65
#define SMEM_BS_FLOATS (256 * 128)
#define SMEM_AS_ULL (2 * 16 * AS_STRIDE)
#define SMEM_TOTAL_BYTES (SMEM_BS_FLOATS * 4 + SMEM_AS_ULL * 8 + 3 * 128 * 4)

// ---------------- fused GEMM + epilogue ----------------
// Z = [x | agg] @ [w1_0 ; w1_1]  (M=n, K=256, N=128), then
// h = relu(Z + b1);  p = h.w2_0;  g = h.w2_1   (h never stored)
// Block: 64 nodes x 128 cols, 256 threads (16x16), thread = 4 nodes x 4 col-pairs
__global__ __launch_bounds__(256, 1) void k_gemm(
    const float* __restrict__ x,
    const float* __restrict__ w10, const float* __restrict__ w11,
    const float* __restrict__ b1,
    const float* __restrict__ w20, const float* __restrict__ w21, int n)
{
    extern __shared__ float sm[];
    float* Bs = sm;                                          // [256][128]
    unsigned long long* As2 = (unsigned long long*)(sm + SMEM_BS_FLOATS);  // [2][16][65] ull
    float* sb1 = (float*)(As2 + SMEM_AS_ULL);                // [128]
    float* sw20 = sb1 + 128;                                 // [128]
    float* sw21 = sw20 + 128;                                // [128]

    int tid = threadIdx.x;
    int tx = tid & 15, ty = tid >> 4;
    int m0 = blockIdx.x * 64;

    // Load W into smem: rows 0..127 = w1_0, 128..255 = w1_1 (each 128x128 row-major)
    {
        float4* bsv = (float4*)Bs;
        const float4* a = (const float4*)w10;
        const float4* b = (const float4*)w11;
        #pragma unroll
        for (int i = 0; i < 16; ++i) bsv[tid + 256 * i] = a[tid + 256 * i];
        #pragma unroll
        for (int i = 0; i < 16; ++i) bsv[4096 + tid + 256 * i] = b[tid + 256 * i];
    }
    if (tid < 128) { sb1[tid] = b1[tid]; sw20[tid] = w20[tid]; sw21[tid] = w21[tid]; }

    // A-tile loader mapping: 256 threads -> 64 rows x 4 quads of 4 k-values
    int arow = tid >> 2, aq = tid & 3;
    int gm = m0 + arow;
    int gmc = (gm < n) ? gm : (n - 1);
    const float* xrow = x + (size_t)gmc * 128;
    const float* grow = g_agg + (size_t)gmc * 128;

    // preload tile 0 (k 0..15 of x) -- duplicated stores
    {
        float4 av = *(const float4*)(xrow + aq * 4);
        unsigned long long* Aw = As2;  // buf 0
        Aw[(aq * 4 + 0) * AS_STRIDE + arow] = pk2(av.x);
        Aw[(aq * 4 + 1) * AS_STRIDE + arow] = pk2(av.y);
        Aw[(aq * 4 + 2) * AS_STRIDE + arow] = pk2(av.z);
        Aw[(aq * 4 + 3) * AS_STRIDE + arow] = pk2(av.w);
    }
    __syncthreads();

    unsigned long long acc[4][4];
    #pragma unroll
    for (int i = 0; i < 4; ++i)
        #pragma unroll
        for (int j = 0; j < 4; ++j) acc[i][j] = 0ULL;

    int buf = 0;
    #pragma unroll 1
    for (int t = 0; t < 16; ++t) {
        float4 nxt;
        if (t < 15) {
            int tk = t + 1;
            const float* srcrow = (tk < 8) ? xrow : grow;
            nxt = *(const float4*)(srcrow + ((tk & 7) * 16 + aq * 4));
        }
        const unsigned long long* Ab = As2 + buf * 16 * AS_STRIDE;
        const float* Bb = Bs + (t * 16) * 128;
        #pragma unroll
        for (int kk = 0; kk < 16; ++kk) {
            const unsigned long long* arow_p = Ab + kk * AS_STRIDE;
            unsigned long long ap0 = arow_p[ty];
            unsigned long long ap1 = arow_p[ty + 16];
            unsigned long long ap2 = arow_p[ty + 32];
            unsigned long long ap3 = arow_p[ty + 48];
            const unsigned long long* brow = (const unsigned long long*)(Bb + kk * 128);
            unsigned long long b0 = brow[tx];        // cols 2tx, 2tx+1
            unsigned long long b1v = brow[tx + 16];  // cols 2tx+32, ..
            unsigned long long b2v = brow[tx + 32];  // cols 2tx+64
            unsigned long long b3v = brow[tx + 48];  // cols 2tx+96
            fma2(acc[0][0], ap0, b0); fma2(acc[0][1], ap0, b1v);
            fma2(acc[0][2], ap0, b2v); fma2(acc[0][3], ap0, b3v);
            fma2(acc[1][0], ap1, b0); fma2(acc[1][1], ap1, b1v);
            fma2(acc[1][2], ap1, b2v); fma2(acc[1][3], ap1, b3v);
            fma2(acc[2][0], ap2, b0); fma2(acc[2][1], ap2, b1v);
            fma2(acc[2][2], ap2, b2v); fma2(acc[2][3], ap2, b3v);
            fma2(acc[3][0], ap3, b0); fma2(acc[3][1], ap3, b1v);
            fma2(acc[3][2], ap3, b2v); fma2(acc[3][3], ap3, b3v);
        }
        if (t < 15) {
            // safe: buf^1 was last read in iter t-1 (barrier at end of t-1)
            unsigned long long* Aw = As2 + (buf ^ 1) * 16 * AS_STRIDE;
            Aw[(aq * 4 + 0) * AS_STRIDE + arow] = pk2(nxt.x);
            Aw[(aq * 4 + 1) * AS_STRIDE + arow] = pk2(nxt.y);
            Aw[(aq * 4 + 2) * AS_STRIDE + arow] = pk2(nxt.z);
            Aw[(aq * 4 + 3) * AS_STRIDE + arow] = pk2(nxt.w);
            buf ^= 1;
        }
        __syncthreads();
    }

    // Epilogue: bias + relu + dots with w2_0/w2_1, reduce over the 16 tx lanes
    #pragma unroll
    for (int i = 0; i < 4; ++i) {
        int m = m0 + ty + 16 * i;
        float p = 0.f, g = 0.f;
        #pragma unroll
        for (int j = 0; j < 4; ++j) {
            float2 v = upk(acc[i][j]);
            int c = 2 * tx + 32 * j;
            float h0 = fmaxf(v.x + sb1[c], 0.f);
            float h1 = fmaxf(v.y + sb1[c + 1], 0.f);
            p = fmaf(h0, sw20[c], fmaf(h1, sw20[c + 1], p));
            g = fmaf(h0, sw21[c], fmaf(h1, sw21[c + 1], g));
        }
        #pragma unroll
        for (int off = 8; off >= 1; off >>= 1) {
            p += __shfl_xor_sync(0xffffffffu, p, off);
            g += __shfl_xor_sync(0xffffffffu, g, off);
        }
        if (tx == 0 && m < n) { g_p[m] = p; g_g[m] = g; }
    }
}

// ---------------- layer-2 scalar scatter: acc[dst] += norm * g[src] ----------------
#define SS_U 4
__global__ void k_scatter_scalar(const int* __restrict__ src,
                                 const int* __restrict__ dst, int E) {
    int base = (blockIdx.x * blockDim.x + threadIdx.x) * SS_U;
    if (base >= E) return;
    int s[SS_U], d[SS_U];
    #pragma unroll
    for (int u = 0; u < SS_U; ++u) {
        int e = base + u;
        e = (e < E) ? e : (E - 1);
        s[u] = __ldg(&src[e]);
        d[u] = __ldg(&dst[e]);
    }
    float v[SS_U];
    #pragma unroll
    for (int u = 0; u < SS_U; ++u)
        v[u] = -g_dinv[s[u]] * g_dinv[d[u]] * g_g[s[u]];
    #pragma unroll
    for (int u = 0; u < SS_U; ++u)
        if (base + u < E) atomicAdd(&g_acc[d[u]], v[u]);
}

// ---------------- output: sigmoid(p + acc + b2) ----------------
__global__ void k_out(const float* __restrict__ b2, float* __restrict__ out, int n) {
    int i = blockIdx.x * blockDim.x + threadIdx.x;
    if (i < n) {
        float z = g_p[i] + g_acc[i] + b2[0];
        out[i] = 1.0f / (1.0f + expf(-z));
    }
}

extern "C" void kernel_launch(void* const* d_in, const int* in_sizes, int n_in,
                              void* d_out, int out_size) {
    const float* x   = (const float*)d_in[0];
    const int*   ei  = (const int*)d_in[1];
    const float* w10 = (const float*)d_in[2];
    const float* w11 = (const float*)d_in[3];
    const float* b1  = (const float*)d_in[4];
    const float* w20 = (const float*)d_in[5];
    const float* w21 = (const float*)d_in[6];
    const float* b2  = (const float*)d_in[7];
    float* out = (float*)d_out;

    int n = in_sizes[0] / 128;
    int E = in_sizes[1] / 2;
    const int* src = ei;
    const int* dst = ei + E;

    k_zero<<<2048, 256>>>(n);
    k_deg<<<(E + 255) / 256, 256>>>(src, E);
    k_dinv<<<(n + 255) / 256, 256>>>(n);

    // 8 warps/block, SC_U edges per warp
    int edges_per_block = 8 * SC_U;
    k_scatter_vec<<<(E + edges_per_block - 1) / edges_per_block, 256>>>(
        (const float4*)x, src, dst, E);

    cudaFuncSetAttribute(k_gemm, cudaFuncAttributeMaxDynamicSharedMemorySize,
                         SMEM_TOTAL_BYTES);
    k_gemm<<<(n + 63) / 64, 256, SMEM_TOTAL_BYTES>>>(x, w10, w11, b1, w20, w21, n);

    k_scatter_scalar<<<(E + 256 * SS_U - 1) / (256 * SS_U), 256>>>(src, dst, E);
    k_out<<<(n + 255) / 256, 256>>>(b2, out, n);
}

// round 4
// speedup vs baseline: 1.3529x; 1.2422x over previous
#include <cuda_runtime.h>

// Problem-fixed maxima (setup_inputs: N=100000, E=1600000, F=H=128)
#define MAX_N 100000
#define MAX_E 1600000
#define MAX_NPAD 100352   // 98 * 1024 >= MAX_N + 1

// -------- scratch (static device globals; no allocation) --------
__device__ __align__(16) int   g_srcdeg[MAX_N];          // out-degree (for dinv)
__device__ __align__(16) float g_dinv[MAX_N];
__device__ __align__(16) int   g_cnt[MAX_NPAD];          // in-degree histogram (padded)
__device__ __align__(16) int   g_ptr[MAX_NPAD];          // CSR row pointers (exclusive scan)
__device__ __align__(16) int   g_pos[MAX_NPAD];          // working copy for placement
__device__ __align__(16) int   g_bsum[256];              // scan block sums
__device__ __align__(16) int   g_esrc[MAX_E];            // CSR: source node per edge
__device__ __align__(16) float g_ew[MAX_E];              // CSR: edge weight -dinv[s]*dinv[d]
__device__ __align__(16) float g_p[MAX_N];               // h . w2_0
__device__ __align__(16) float g_g[MAX_N];               // h . w2_1
__device__ __align__(16) float g_acc[MAX_N];             // layer-2 gathered scalar
__device__ __align__(16) float g_agg[MAX_N * 128];       // A_norm @ x   (51.2 MB)

// ---------------- zero counters ----------------
__global__ void k_zero(int n, int npad) {
    int i = blockIdx.x * blockDim.x + threadIdx.x;
    if (i < n) g_srcdeg[i] = 0;
    if (i < npad) g_cnt[i] = 0;
}

// ---------------- histograms: out-degree (src) + in-degree (dst) ----------------
#define HU 4
__global__ void k_hist(const int* __restrict__ src, const int* __restrict__ dst, int E) {
    int base = (blockIdx.x * blockDim.x + threadIdx.x) * HU;
    if (base >= E) return;
    int s[HU], d[HU];
    #pragma unroll
    for (int u = 0; u < HU; ++u) {
        int e = base + u; e = (e < E) ? e : (E - 1);
        s[u] = __ldg(&src[e]); d[u] = __ldg(&dst[e]);
    }
    #pragma unroll
    for (int u = 0; u < HU; ++u)
        if (base + u < E) { atomicAdd(&g_srcdeg[s[u]], 1); atomicAdd(&g_cnt[d[u]], 1); }
}

__global__ void k_dinv(int n) {
    int i = blockIdx.x * blockDim.x + threadIdx.x;
    if (i < n) {
        int d = g_srcdeg[i];
        g_dinv[i] = (d > 0) ? rsqrtf((float)d) : 0.f;
    }
}

// ---------------- exclusive prefix scan over g_cnt (padded) ----------------
// pass 1: per-block (1024 elems = 256 thr x int4) local exclusive scan + block sum
__global__ __launch_bounds__(256) void k_scan_local() {
    __shared__ int ssum[256];
    int b = blockIdx.x, t = threadIdx.x;
    int4 v = ((const int4*)g_cnt)[b * 256 + t];
    int ts = v.x + v.y + v.z + v.w;
    ssum[t] = ts;
    __syncthreads();
    #pragma unroll
    for (int off = 1; off < 256; off <<= 1) {
        int xv = (t >= off) ? ssum[t - off] : 0;
        __syncthreads();
        ssum[t] += xv;
        __syncthreads();
    }
    int excl = ssum[t] - ts;
    int4 o;
    o.x = excl; o.y = excl + v.x; o.z = o.y + v.y; o.w = o.z + v.z;
    ((int4*)g_ptr)[b * 256 + t] = o;
    if (t == 255) g_bsum[b] = ssum[255];
}

// pass 2: exclusive scan of block sums (nb <= 256), single block
__global__ __launch_bounds__(256) void k_scan_bsum(int nb) {
    __shared__ int sb[256];
    int t = threadIdx.x;
    int v = (t < nb) ? g_bsum[t] : 0;
    sb[t] = v;
    __syncthreads();
    #pragma unroll
    for (int off = 1; off < 256; off <<= 1) {
        int xv = (t >= off) ? sb[t - off] : 0;
        __syncthreads();
        sb[t] += xv;
        __syncthreads();
    }
    if (t < nb) g_bsum[t] = sb[t] - v;   // exclusive
}

// pass 3: add block offsets, write g_ptr final + g_pos working copy
__global__ __launch_bounds__(256) void k_scan_add() {
    int b = blockIdx.x, t = threadIdx.x;
    int off = g_bsum[b];
    int4 v = ((const int4*)g_ptr)[b * 256 + t];
    v.x += off; v.y += off; v.z += off; v.w += off;
    ((int4*)g_ptr)[b * 256 + t] = v;
    ((int4*)g_pos)[b * 256 + t] = v;
}

// ---------------- place edges into CSR buckets ----------------
#define PU 4
__global__ void k_place(const int* __restrict__ src, const int* __restrict__ dst, int E) {
    int base = (blockIdx.x * blockDim.x + threadIdx.x) * PU;
    if (base >= E) return;
    int s[PU], d[PU];
    #pragma unroll
    for (int u = 0; u < PU; ++u) {
        int e = base + u; e = (e < E) ? e : (E - 1);
        s[u] = __ldg(&src[e]); d[u] = __ldg(&dst[e]);
    }
    float w[PU];
    #pragma unroll
    for (int u = 0; u < PU; ++u)
        w[u] = -g_dinv[s[u]] * g_dinv[d[u]];
    #pragma unroll
    for (int u = 0; u < PU; ++u) {
        if (base + u < E) {
            int pos = atomicAdd(&g_pos[d[u]], 1);
            g_esrc[pos] = s[u];
            g_ew[pos] = w[u];
        }
    }
}

// ---------------- layer-1 gather: agg[d] = sum_e w_e * x[src_e] ----------------
// one warp per node; lane covers 4 contiguous features; edges unrolled x4 for MLP
__global__ __launch_bounds__(256) void k_gather(const float4* __restrict__ x4, int n) {
    int node = (blockIdx.x * blockDim.x + threadIdx.x) >> 5;
    int lane = threadIdx.x & 31;
    if (node >= n) return;
    int beg = __ldg(&g_ptr[node]);
    int end = __ldg(&g_ptr[node + 1]);
    float4 acc = make_float4(0.f, 0.f, 0.f, 0.f);
    int e = beg;
    for (; e + 4 <= end; e += 4) {
        int s0 = __ldg(&g_esrc[e]),     s1 = __ldg(&g_esrc[e + 1]);
        int s2 = __ldg(&g_esrc[e + 2]), s3 = __ldg(&g_esrc[e + 3]);
        float w0 = __ldg(&g_ew[e]),     w1 = __ldg(&g_ew[e + 1]);
        float w2 = __ldg(&g_ew[e + 2]), w3 = __ldg(&g_ew[e + 3]);
        float4 v0 = x4[(size_t)s0 * 32 + lane];
        float4 v1 = x4[(size_t)s1 * 32 + lane];
        float4 v2 = x4[(size_t)s2 * 32 + lane];
        float4 v3 = x4[(size_t)s3 * 32 + lane];
        acc.x = fmaf(w0, v0.x, fmaf(w1, v1.x, fmaf(w2, v2.x, fmaf(w3, v3.x, acc.x))));
        acc.y = fmaf(w0, v0.y, fmaf(w1, v1.y, fmaf(w2, v2.y, fmaf(w3, v3.y, acc.y))));
        acc.z = fmaf(w0, v0.z, fmaf(w1, v1.z, fmaf(w2, v2.z, fmaf(w3, v3.z, acc.z))));
        acc.w = fmaf(w0, v0.w, fmaf(w1, v1.w, fmaf(w2, v2.w, fmaf(w3, v3.w, acc.w))));
    }
    for (; e < end; ++e) {
        int s = __ldg(&g_esrc[e]);
        float w = __ldg(&g_ew[e]);
        float4 v = x4[(size_t)s * 32 + lane];
        acc.x = fmaf(w, v.x, acc.x); acc.y = fmaf(w, v.y, acc.y);
        acc.z = fmaf(w, v.z, acc.z); acc.w = fmaf(w, v.w, acc.w);
    }
    ((float4*)g_agg)[(size_t)node * 32 + lane] = acc;
}

// ---------------- packed-f32x2 helpers ----------------
__device__ __forceinline__ void fma2(unsigned long long& acc, unsigned long long a,
                                     unsigned long long b) {
    asm("fma.rn.f32x2 %0, %1, %2, %0;" : "+l"(acc) : "l"(a), "l"(b));
}
__device__ __forceinline__ unsigned long long pk2(float v) {
    unsigned long long r;
    asm("mov.b64 %0, {%1, %1};" : "=l"(r) : "f"(v));
    return r;
}
__device__ __forceinline__ float2 upk(unsigned long long v) {
    float2 r;
    asm("mov.b64 {%0, %1}, %2;" : "=f"(r.x), "=f"(r.y) : "l"(v));
    return r;
}

// A tile stored PRE-DUPLICATED as f32x2 (ull) pairs: As2[buf][k][row], stride 65 ull
#define AS_STRIDE 65
#define SMEM_BS_FLOATS (256 * 128)
#define SMEM_AS_ULL (2 * 16 * AS_STRIDE)
#define SMEM_TOTAL_BYTES (SMEM_BS_FLOATS * 4 + SMEM_AS_ULL * 8 + 3 * 128 * 4)

// ---------------- fused GEMM + epilogue ----------------
// Z = [x | agg] @ [w1_0 ; w1_1]  (M=n, K=256, N=128), then
// h = relu(Z + b1);  p = h.w2_0;  g = h.w2_1   (h never stored)
__global__ __launch_bounds__(256, 1) void k_gemm(
    const float* __restrict__ x,
    const float* __restrict__ w10, const float* __restrict__ w11,
    const float* __restrict__ b1,
    const float* __restrict__ w20, const float* __restrict__ w21, int n)
{
    extern __shared__ float sm[];
    float* Bs = sm;                                          // [256][128]
    unsigned long long* As2 = (unsigned long long*)(sm + SMEM_BS_FLOATS);  // [2][16][65]
    float* sb1 = (float*)(As2 + SMEM_AS_ULL);                // [128]
    float* sw20 = sb1 + 128;
    float* sw21 = sw20 + 128;

    int tid = threadIdx.x;
    int tx = tid & 15, ty = tid >> 4;
    int m0 = blockIdx.x * 64;

    {
        float4* bsv = (float4*)Bs;
        const float4* a = (const float4*)w10;
        const float4* b = (const float4*)w11;
        #pragma unroll
        for (int i = 0; i < 16; ++i) bsv[tid + 256 * i] = a[tid + 256 * i];
        #pragma unroll
        for (int i = 0; i < 16; ++i) bsv[4096 + tid + 256 * i] = b[tid + 256 * i];
    }
    if (tid < 128) { sb1[tid] = b1[tid]; sw20[tid] = w20[tid]; sw21[tid] = w21[tid]; }

    int arow = tid >> 2, aq = tid & 3;
    int gm = m0 + arow;
    int gmc = (gm < n) ? gm : (n - 1);
    const float* xrow = x + (size_t)gmc * 128;
    const float* grow = g_agg + (size_t)gmc * 128;

    {
        float4 av = *(const float4*)(xrow + aq * 4);
        unsigned long long* Aw = As2;  // buf 0
        Aw[(aq * 4 + 0) * AS_STRIDE + arow] = pk2(av.x);
        Aw[(aq * 4 + 1) * AS_STRIDE + arow] = pk2(av.y);
        Aw[(aq * 4 + 2) * AS_STRIDE + arow] = pk2(av.z);
        Aw[(aq * 4 + 3) * AS_STRIDE + arow] = pk2(av.w);
    }
    __syncthreads();

    unsigned long long acc[4][4];
    #pragma unroll
    for (int i = 0; i < 4; ++i)
        #pragma unroll
        for (int j = 0; j < 4; ++j) acc[i][j] = 0ULL;

    int buf = 0;
    #pragma unroll 1
    for (int t = 0; t < 16; ++t) {
        float4 nxt;
        if (t < 15) {
            int tk = t + 1;
            const float* srcrow = (tk < 8) ? xrow : grow;
            nxt = *(const float4*)(srcrow + ((tk & 7) * 16 + aq * 4));
        }
        const unsigned long long* Ab = As2 + buf * 16 * AS_STRIDE;
        const float* Bb = Bs + (t * 16) * 128;
        #pragma unroll
        for (int kk = 0; kk < 16; ++kk) {
            const unsigned long long* arow_p = Ab + kk * AS_STRIDE;
            unsigned long long ap0 = arow_p[ty];
            unsigned long long ap1 = arow_p[ty + 16];
            unsigned long long ap2 = arow_p[ty + 32];
            unsigned long long ap3 = arow_p[ty + 48];
            const unsigned long long* brow = (const unsigned long long*)(Bb + kk * 128);
            unsigned long long b0 = brow[tx];
            unsigned long long b1v = brow[tx + 16];
            unsigned long long b2v = brow[tx + 32];
            unsigned long long b3v = brow[tx + 48];
            fma2(acc[0][0], ap0, b0); fma2(acc[0][1], ap0, b1v);
            fma2(acc[0][2], ap0, b2v); fma2(acc[0][3], ap0, b3v);
            fma2(acc[1][0], ap1, b0); fma2(acc[1][1], ap1, b1v);
            fma2(acc[1][2], ap1, b2v); fma2(acc[1][3], ap1, b3v);
            fma2(acc[2][0], ap2, b0); fma2(acc[2][1], ap2, b1v);
            fma2(acc[2][2], ap2, b2v); fma2(acc[2][3], ap2, b3v);
            fma2(acc[3][0], ap3, b0); fma2(acc[3][1], ap3, b1v);
            fma2(acc[3][2], ap3, b2v); fma2(acc[3][3], ap3, b3v);
        }
        if (t < 15) {
            unsigned long long* Aw = As2 + (buf ^ 1) * 16 * AS_STRIDE;
            Aw[(aq * 4 + 0) * AS_STRIDE + arow] = pk2(nxt.x);
            Aw[(aq * 4 + 1) * AS_STRIDE + arow] = pk2(nxt.y);
            Aw[(aq * 4 + 2) * AS_STRIDE + arow] = pk2(nxt.z);
            Aw[(aq * 4 + 3) * AS_STRIDE + arow] = pk2(nxt.w);
            buf ^= 1;
        }
        __syncthreads();
    }

    #pragma unroll
    for (int i = 0; i < 4; ++i) {
        int m = m0 + ty + 16 * i;
        float p = 0.f, g = 0.f;
        #pragma unroll
        for (int j = 0; j < 4; ++j) {
            float2 v = upk(acc[i][j]);
            int c = 2 * tx + 32 * j;
            float h0 = fmaxf(v.x + sb1[c], 0.f);
            float h1 = fmaxf(v.y + sb1[c + 1], 0.f);
            p = fmaf(h0, sw20[c], fmaf(h1, sw20[c + 1], p));
            g = fmaf(h0, sw21[c], fmaf(h1, sw21[c + 1], g));
        }
        #pragma unroll
        for (int off = 8; off >= 1; off >>= 1) {
            p += __shfl_xor_sync(0xffffffffu, p, off);
            g += __shfl_xor_sync(0xffffffffu, g, off);
        }
        if (tx == 0 && m < n) { g_p[m] = p; g_g[m] = g; }
    }
}

// ---------------- layer-2 gather: acc[d] = sum_e w_e * g[src_e] ----------------
// one warp per node; lanes stride over edge list; shuffle reduce
__global__ __launch_bounds__(256) void k_gather2(int n) {
    int node = (blockIdx.x * blockDim.x + threadIdx.x) >> 5;
    int lane = threadIdx.x & 31;
    if (node >= n) return;
    int beg = __ldg(&g_ptr[node]);
    int end = __ldg(&g_ptr[node + 1]);
    float a = 0.f;
    for (int e = beg + lane; e < end; e += 32)
        a = fmaf(__ldg(&g_ew[e]), __ldg(&g_g[__ldg(&g_esrc[e])]), a);
    #pragma unroll
    for (int off = 16; off >= 1; off >>= 1)
        a += __shfl_xor_sync(0xffffffffu, a, off);
    if (lane == 0) g_acc[node] = a;
}

// ---------------- output: sigmoid(p + acc + b2) ----------------
__global__ void k_out(const float* __restrict__ b2, float* __restrict__ out, int n) {
    int i = blockIdx.x * blockDim.x + threadIdx.x;
    if (i < n) {
        float z = g_p[i] + g_acc[i] + b2[0];
        out[i] = 1.0f / (1.0f + expf(-z));
    }
}

extern "C" void kernel_launch(void* const* d_in, const int* in_sizes, int n_in,
                              void* d_out, int out_size) {
    const float* x   = (const float*)d_in[0];
    const int*   ei  = (const int*)d_in[1];
    const float* w10 = (const float*)d_in[2];
    const float* w11 = (const float*)d_in[3];
    const float* b1  = (const float*)d_in[4];
    const float* w20 = (const float*)d_in[5];
    const float* w21 = (const float*)d_in[6];
    const float* b2  = (const float*)d_in[7];
    float* out = (float*)d_out;

    int n = in_sizes[0] / 128;
    int E = in_sizes[1] / 2;
    const int* src = ei;
    const int* dst = ei + E;

    int nb = (n + 1 + 1023) / 1024;       // scan blocks (1024 elems each), covers ptr[n]
    int npad = nb * 1024;

    k_zero<<<(npad + 255) / 256, 256>>>(n, npad);
    k_hist<<<(E + 256 * HU - 1) / (256 * HU), 256>>>(src, dst, E);
    k_dinv<<<(n + 255) / 256, 256>>>(n);
    k_scan_local<<<nb, 256>>>();
    k_scan_bsum<<<1, 256>>>(nb);
    k_scan_add<<<nb, 256>>>();
    k_place<<<(E + 256 * PU - 1) / (256 * PU), 256>>>(src, dst, E);
    k_gather<<<(n * 32 + 255) / 256, 256>>>((const float4*)x, n);

    cudaFuncSetAttribute(k_gemm, cudaFuncAttributeMaxDynamicSharedMemorySize,
                         SMEM_TOTAL_BYTES);
    k_gemm<<<(n + 63) / 64, 256, SMEM_TOTAL_BYTES>>>(x, w10, w11, b1, w20, w21, n);

    k_gather2<<<(n * 32 + 255) / 256, 256>>>(n);
    k_out<<<(n + 255) / 256, 256>>>(b2, out, n);
}